// round 2
// baseline (speedup 1.0000x reference)
#include <cuda_runtime.h>
#include <math.h>

#define NB    32
#define CH    512
#define WD    28
#define HDIM  28
#define NPIX  784
#define HEADS 8
#define DH    64

// Scratch (static __device__ — no allocations allowed)
__device__ float g_q[NB*CH*NPIX];      // [b][o][n]
__device__ float g_k[NB*CH*NPIX];      // [b][o][n]
__device__ float g_vT[NB*NPIX*CH];     // [b][n][o]  (transposed for coalesced V tiles)
__device__ float g_pos[HEADS*DH*NPIX]; // [h*64+d][n]

// ---------------------------------------------------------------------------
// pos[h,d,n] = rel_h[h,d,n%28] + rel_w[h,d,n/28]
// ---------------------------------------------------------------------------
__global__ void pos_kernel(const float* __restrict__ rel_h,
                           const float* __restrict__ rel_w) {
    int idx = blockIdx.x * 256 + threadIdx.x;
    if (idx >= HEADS*DH*NPIX) return;
    int n  = idx % NPIX;
    int hd = idx / NPIX;
    g_pos[idx] = rel_h[hd*HDIM + (n % HDIM)] + rel_w[hd*WD + (n / HDIM)];
}

// ---------------------------------------------------------------------------
// Projection GEMM: Y[o,n] = sum_c W[o,c] X[c,n] + bias[o], per batch.
// 64x64 tiles, K-tile 32, 256 threads, 4x4 micro-tiles.
// WHICH: 0->g_q, 1->g_k, 2->g_vT (transposed store)
// ---------------------------------------------------------------------------
template<int WHICH>
__global__ void proj_kernel(const float* __restrict__ X,
                            const float* __restrict__ Wt,
                            const float* __restrict__ bias) {
    __shared__ float Ws[32][68];  // [c][o]
    __shared__ float Xs[32][68];  // [c][n]

    const int b  = blockIdx.z;
    const int o0 = blockIdx.y * 64;
    const int n0 = blockIdx.x * 64;
    const int tid = threadIdx.x;
    const int tx = tid & 15, ty = tid >> 4;
    const float* Xb = X + b*CH*NPIX;

    float acc[4][4] = {};

    for (int c0 = 0; c0 < CH; c0 += 32) {
        #pragma unroll
        for (int i = 0; i < 8; i++) {           // 64x32 W tile -> transposed
            int idx = tid + i*256;
            int o = idx >> 5, c = idx & 31;
            Ws[c][o] = Wt[(o0+o)*CH + c0 + c];
        }
        #pragma unroll
        for (int i = 0; i < 8; i++) {           // 32x64 X tile
            int idx = tid + i*256;
            int c = idx >> 6, n = idx & 63;
            int gn = n0 + n;
            Xs[c][n] = (gn < NPIX) ? Xb[(c0+c)*NPIX + gn] : 0.f;
        }
        __syncthreads();
        #pragma unroll
        for (int kk = 0; kk < 32; kk++) {
            float4 wf = *(const float4*)&Ws[kk][ty*4];
            float4 xf = *(const float4*)&Xs[kk][tx*4];
            float wr[4] = {wf.x, wf.y, wf.z, wf.w};
            float xr[4] = {xf.x, xf.y, xf.z, xf.w};
            #pragma unroll
            for (int r = 0; r < 4; r++)
                #pragma unroll
                for (int c = 0; c < 4; c++)
                    acc[r][c] += wr[r] * xr[c];
        }
        __syncthreads();
    }

    if (WHICH < 2) {
        float* Y = (WHICH == 0) ? g_q : g_k;
        #pragma unroll
        for (int r = 0; r < 4; r++) {
            int o = o0 + ty*4 + r;
            float bv = bias[o];
            int n = n0 + tx*4;
            float* dst = Y + (b*CH + o)*NPIX + n;
            if (n + 3 < NPIX) {
                float4 v = {acc[r][0]+bv, acc[r][1]+bv, acc[r][2]+bv, acc[r][3]+bv};
                *(float4*)dst = v;
            } else {
                #pragma unroll
                for (int c = 0; c < 4; c++)
                    if (n + c < NPIX) dst[c] = acc[r][c] + bv;
            }
        }
    } else {
        float b0 = bias[o0+ty*4+0], b1 = bias[o0+ty*4+1];
        float b2 = bias[o0+ty*4+2], b3 = bias[o0+ty*4+3];
        #pragma unroll
        for (int c = 0; c < 4; c++) {
            int n = n0 + tx*4 + c;
            if (n < NPIX) {
                float4 v = {acc[0][c]+b0, acc[1][c]+b1, acc[2][c]+b2, acc[3][c]+b3};
                *(float4*)&g_vT[(b*NPIX + n)*CH + o0 + ty*4] = v;
            }
        }
    }
}

// ---------------------------------------------------------------------------
// Fused flash attention.
// Effective Qe_i = [q_i ; pos_i] (128), Ke_j = [k_j ; q_j] (128), V 64-dim.
// Block: one (b,h) pair x one 64-query tile. 256 threads, 4x4 micro-tiles.
// ---------------------------------------------------------------------------
#define QE_OFF 0
#define KE_OFF (128*68)
#define VS_OFF (2*128*68)
#define PS_OFF (2*128*68 + 64*68)
#define ATTN_SMEM_FLOATS (2*128*68 + 2*64*68)

__global__ void attn_kernel(float* __restrict__ out) {
    extern __shared__ float sm[];
    float* Qe = sm + QE_OFF;   // [dim 128][i 64] pad 68
    float* Ke = sm + KE_OFF;   // [dim 128][j 64]
    float* Vs = sm + VS_OFF;   // [j 64][d 64]
    float* Ps = sm + PS_OFF;   // [j 64][i 64]

    const int tid = threadIdx.x;
    const int tx = tid & 15, ty = tid >> 4;
    const int bh = blockIdx.y;
    const int b = bh >> 3, h = bh & 7;
    const int i0 = blockIdx.x * 64;

    const float* qb = g_q + (b*CH + h*DH)*NPIX;
    const float* kb = g_k + (b*CH + h*DH)*NPIX;
    const float* vb = g_vT + b*NPIX*CH + h*DH;
    const float* pb = g_pos + h*DH*NPIX;

    // Load Qe tile once: dims 0..63 = q, 64..127 = pos
    #pragma unroll
    for (int it = 0; it < 32; it++) {
        int idx = tid + it*256;
        int dim = idx >> 6, i = idx & 63;
        int gi = i0 + i;
        float v = 0.f;
        if (gi < NPIX)
            v = (dim < DH) ? qb[dim*NPIX + gi] : pb[(dim-DH)*NPIX + gi];
        Qe[dim*68 + i] = v;
    }

    float m[4], l[4], o_acc[4][4];
    #pragma unroll
    for (int r = 0; r < 4; r++) {
        m[r] = -INFINITY; l[r] = 0.f;
        #pragma unroll
        for (int c = 0; c < 4; c++) o_acc[r][c] = 0.f;
    }

    for (int jt = 0; jt < 13; jt++) {
        const int j0 = jt * 64;
        __syncthreads();   // protect Ke/Vs/Ps consumers from previous iter

        #pragma unroll
        for (int it = 0; it < 32; it++) {   // Ke: dims 0..63 = k, 64..127 = q
            int idx = tid + it*256;
            int dim = idx >> 6, j = idx & 63;
            int gj = j0 + j;
            float v = 0.f;
            if (gj < NPIX)
                v = (dim < DH) ? kb[dim*NPIX + gj] : qb[(dim-DH)*NPIX + gj];
            Ke[dim*68 + j] = v;
        }
        #pragma unroll
        for (int it = 0; it < 16; it++) {   // Vs[j][d] from transposed v
            int idx = tid + it*256;
            int j = idx >> 6, d = idx & 63;
            int gj = j0 + j;
            Vs[j*68 + d] = (gj < NPIX) ? vb[gj*CH + d] : 0.f;
        }
        __syncthreads();

        // S = Qe^T Ke  (64x64, K=128)
        float s[4][4] = {};
        #pragma unroll 8
        for (int dim = 0; dim < 128; dim++) {
            float4 qf = *(const float4*)&Qe[dim*68 + ty*4];
            float4 kf = *(const float4*)&Ke[dim*68 + tx*4];
            float qr[4] = {qf.x, qf.y, qf.z, qf.w};
            float kr[4] = {kf.x, kf.y, kf.z, kf.w};
            #pragma unroll
            for (int r = 0; r < 4; r++)
                #pragma unroll
                for (int c = 0; c < 4; c++)
                    s[r][c] += qr[r] * kr[c];
        }

        if (j0 + 64 > NPIX) {     // mask invalid keys in tail tile
            #pragma unroll
            for (int c = 0; c < 4; c++)
                if (j0 + tx*4 + c >= NPIX) {
                    #pragma unroll
                    for (int r = 0; r < 4; r++) s[r][c] = -INFINITY;
                }
        }

        // Online softmax (row groups = 16 lanes sharing ty)
        #pragma unroll
        for (int r = 0; r < 4; r++) {
            float mx = fmaxf(fmaxf(s[r][0], s[r][1]), fmaxf(s[r][2], s[r][3]));
            #pragma unroll
            for (int off = 8; off > 0; off >>= 1)
                mx = fmaxf(mx, __shfl_xor_sync(0xffffffffu, mx, off));
            float mnew  = fmaxf(m[r], mx);
            float scale = __expf(m[r] - mnew);
            float p0 = __expf(s[r][0] - mnew);
            float p1 = __expf(s[r][1] - mnew);
            float p2 = __expf(s[r][2] - mnew);
            float p3 = __expf(s[r][3] - mnew);
            float rs = (p0 + p1) + (p2 + p3);
            #pragma unroll
            for (int off = 8; off > 0; off >>= 1)
                rs += __shfl_xor_sync(0xffffffffu, rs, off);
            l[r] = l[r]*scale + rs;
            m[r] = mnew;
            #pragma unroll
            for (int c = 0; c < 4; c++) o_acc[r][c] *= scale;
            // store P transposed: Ps[j][i]
            Ps[(tx*4+0)*68 + ty*4 + r] = p0;
            Ps[(tx*4+1)*68 + ty*4 + r] = p1;
            Ps[(tx*4+2)*68 + ty*4 + r] = p2;
            Ps[(tx*4+3)*68 + ty*4 + r] = p3;
        }
        __syncthreads();

        // O += P @ V  (64x64, K=64)
        #pragma unroll 8
        for (int j = 0; j < 64; j++) {
            float4 pf = *(const float4*)&Ps[j*68 + ty*4];
            float4 vf = *(const float4*)&Vs[j*68 + tx*4];
            float pr[4] = {pf.x, pf.y, pf.z, pf.w};
            float vr[4] = {vf.x, vf.y, vf.z, vf.w};
            #pragma unroll
            for (int r = 0; r < 4; r++)
                #pragma unroll
                for (int c = 0; c < 4; c++)
                    o_acc[r][c] += pr[r] * vr[c];
        }
    }

    // Normalize + store: out[b, h*64 + d, i]
    #pragma unroll
    for (int r = 0; r < 4; r++) {
        int i = i0 + ty*4 + r;
        if (i < NPIX) {
            float inv = __fdividef(1.f, l[r]);
            #pragma unroll
            for (int c = 0; c < 4; c++)
                out[(b*CH + h*DH + tx*4 + c)*NPIX + i] = o_acc[r][c] * inv;
        }
    }
}

// ---------------------------------------------------------------------------
extern "C" void kernel_launch(void* const* d_in, const int* in_sizes, int n_in,
                              void* d_out, int out_size) {
    const float* x     = (const float*)d_in[0];
    const float* wq    = (const float*)d_in[1];
    const float* bq    = (const float*)d_in[2];
    const float* wk    = (const float*)d_in[3];
    const float* bk    = (const float*)d_in[4];
    const float* wv    = (const float*)d_in[5];
    const float* bv    = (const float*)d_in[6];
    const float* rel_h = (const float*)d_in[7];
    const float* rel_w = (const float*)d_in[8];
    float* out = (float*)d_out;

    const int attn_smem = ATTN_SMEM_FLOATS * (int)sizeof(float);  // 104448 B
    cudaFuncSetAttribute(attn_kernel,
                         cudaFuncAttributeMaxDynamicSharedMemorySize, attn_smem);

    pos_kernel<<<(HEADS*DH*NPIX + 255)/256, 256>>>(rel_h, rel_w);

    dim3 pgrid(13, 8, NB);   // n-tiles x o-tiles x batch
    proj_kernel<0><<<pgrid, 256>>>(x, wq, bq);
    proj_kernel<1><<<pgrid, 256>>>(x, wk, bk);
    proj_kernel<2><<<pgrid, 256>>>(x, wv, bv);

    dim3 agrid(13, NB*HEADS);  // q-tiles x (b,h)
    attn_kernel<<<agrid, 256, attn_smem>>>(out);
}